// round 2
// baseline (speedup 1.0000x reference)
#include <cuda_runtime.h>
#include <cuda_bf16.h>
#include <cstdint>
#include <math.h>

// ---------------- problem constants ----------------
#define N_IMG 2
#define R_TOT 159882
#define N_LVL 5
#define K_TOT 4507            // 1000+1000+1000+1000+507
#define POST_NMS 1000
#define NMS_THRESH 0.7f
#define IMG_MAX 800.0f
#define MIN_SIZE 1e-3f
#define BBOX_CLIP 4.135166556742356f   // log(1000/16) rounded to f32

__constant__ int c_loff[N_LVL]  = {0, 120000, 150000, 157500, 159375};
__constant__ int c_lsize[N_LVL] = {120000, 30000, 7500, 1875, 507};
__constant__ int c_ksel[N_LVL]  = {1000, 1000, 1000, 1000, 507};
__constant__ int c_soff[N_LVL]  = {0, 1000, 2000, 3000, 4000};

// ---------------- scratch (device globals; no allocation allowed) ----------
__device__ int            g_cand_idx[N_IMG * K_TOT];
__device__ float4         g_cand_box[N_IMG * K_TOT];
__device__ float          g_cand_score[N_IMG * K_TOT];
__device__ unsigned char  g_cand_valid[N_IMG * K_TOT];
__device__ int            g_sorted_slot[N_IMG * K_TOT];
__device__ unsigned char  g_keep[N_IMG * K_TOT];

// ---------------- helpers ----------------
__device__ __forceinline__ unsigned mono_key(float f) {
    unsigned u = __float_as_uint(f);
    return (u & 0x80000000u) ? ~u : (u | 0x80000000u);
}

// block-wide ordered compaction scan (1024 threads): exclusive prefix of flag,
// *total gets block total.
__device__ __forceinline__ int block_scan_flag(bool flag, int* total) {
    __shared__ int wsum[32];
    int lane = threadIdx.x & 31;
    int wid  = threadIdx.x >> 5;
    unsigned ballot = __ballot_sync(0xffffffffu, flag);
    int lane_pref = __popc(ballot & ((1u << lane) - 1u));
    if (lane == 0) wsum[wid] = __popc(ballot);
    __syncthreads();
    if (wid == 0) {
        int v = wsum[lane];
        #pragma unroll
        for (int d = 1; d < 32; d <<= 1) {
            int x = __shfl_up_sync(0xffffffffu, v, d);
            if (lane >= d) v += x;
        }
        wsum[lane] = v;
    }
    __syncthreads();
    int excl = (wid == 0 ? 0 : wsum[wid - 1]) + lane_pref;
    *total = wsum[31];
    __syncthreads();
    return excl;
}

// ---------------- K1: per-(img,level) radix-select top-k ---------------------
// Produces g_cand_idx ordered EXACTLY like lax.top_k: objectness descending,
// ties by ascending original index. So slot == reference candidate position.
__global__ void topk_kernel(const float* __restrict__ obj) {
    const int img = blockIdx.x / N_LVL;
    const int lvl = blockIdx.x % N_LVL;
    const int n    = c_lsize[lvl];
    const int base = c_loff[lvl];
    const int k    = c_ksel[lvl];
    const float* src = obj + img * R_TOT + base;
    const int tid = threadIdx.x;

    __shared__ unsigned hist[2048];
    __shared__ unsigned sfx[2048];
    __shared__ unsigned sh_bstar, sh_kth;
    __shared__ unsigned long long skey[2048];
    __shared__ int c_sel;

    unsigned prefix = 0, pmask = 0, kth = (unsigned)k;
    const int shifts[3] = {21, 10, 0};
    const int nbits[3]  = {11, 11, 10};

    for (int pass = 0; pass < 3; ++pass) {
        const int shift = shifts[pass];
        const int bins  = 1 << nbits[pass];
        const unsigned bm = bins - 1;

        for (int b = tid; b < bins; b += 1024) hist[b] = 0;
        __syncthreads();
        for (int i = tid; i < n; i += 1024) {
            unsigned u = mono_key(src[i]);
            if ((u & pmask) == prefix) atomicAdd(&hist[(u >> shift) & bm], 1u);
        }
        __syncthreads();
        for (int b = tid; b < bins; b += 1024) sfx[b] = hist[b];
        __syncthreads();
        for (int d = 1; d < bins; d <<= 1) {           // suffix sums
            unsigned v0 = 0, v1 = 0;
            int b0 = tid, b1 = tid + 1024;
            if (b0 < bins) v0 = sfx[b0] + ((b0 + d < bins) ? sfx[b0 + d] : 0u);
            if (b1 < bins) v1 = sfx[b1] + ((b1 + d < bins) ? sfx[b1 + d] : 0u);
            __syncthreads();
            if (b0 < bins) sfx[b0] = v0;
            if (b1 < bins) sfx[b1] = v1;
            __syncthreads();
        }
        for (int b = tid; b < bins; b += 1024) {
            unsigned above = (b + 1 < bins) ? sfx[b + 1] : 0u;
            if (sfx[b] >= kth && above < kth) {
                sh_bstar = (unsigned)b;
                sh_kth   = kth - above;
            }
        }
        __syncthreads();
        prefix |= sh_bstar << shift;
        pmask  |= bm << shift;
        kth = sh_kth;
        __syncthreads();
    }

    const unsigned T = prefix;   // exact mono key of k-th largest

    // collect ALL elements with key >= T (count may slightly exceed k on ties)
    for (int t = tid; t < 2048; t += 1024) skey[t] = 0ull;
    if (tid == 0) c_sel = 0;
    __syncthreads();
    for (int i = tid; i < n; i += 1024) {
        unsigned u = mono_key(src[i]);
        if (u >= T) {
            int p = atomicAdd(&c_sel, 1);
            if (p < 2048)
                skey[p] = ((unsigned long long)u << 17) | (unsigned)(131071 - i);
        }
    }
    __syncthreads();

    // bitonic sort ascending over 2048 (1024 threads, 1 pair each)
    for (int k2 = 2; k2 <= 2048; k2 <<= 1) {
        for (int j = k2 >> 1; j > 0; j >>= 1) {
            int i2 = ((tid & ~(j - 1)) << 1) | (tid & (j - 1));
            int p2 = i2 + j;
            bool dir = ((i2 & k2) == 0);
            unsigned long long A = skey[i2], B = skey[p2];
            if ((A > B) == dir) { skey[i2] = B; skey[p2] = A; }
            __syncthreads();
        }
    }

    // t-th largest key = skey[2047 - t]: objectness desc, index asc on ties
    const int soff = img * K_TOT + c_soff[lvl];
    for (int t = tid; t < k; t += 1024) {
        unsigned long long key = skey[2047 - t];
        int i = 131071 - (int)(key & 0x1FFFFull);
        g_cand_idx[soff + t] = base + i;
    }
}

// ---------------- K2: gather + decode + clip + validity ----------------------
// Strictly unfused f32 arithmetic to mirror XLA elementwise ops.
__global__ void decode_kernel(const float* __restrict__ obj,
                              const float* __restrict__ deltas,
                              const float* __restrict__ anchors) {
    int t = blockIdx.x * blockDim.x + threadIdx.x;
    if (t >= N_IMG * K_TOT) return;
    const int img = t / K_TOT;
    g_keep[t] = 0;

    const int r = g_cand_idx[t];
    const float o = obj[img * R_TOT + r];
    // XLA logistic: 1 / (1 + exp(-x)), libdevice expf, rn add/div
    const float score = __fdiv_rn(1.0f, __fadd_rn(1.0f, expf(-o)));

    const float* a = anchors + 4 * r;
    const float ax1 = a[0], ay1 = a[1], ax2 = a[2], ay2 = a[3];
    const float wa = __fsub_rn(ax2, ax1);
    const float ha = __fsub_rn(ay2, ay1);
    const float cxa = __fadd_rn(ax1, __fmul_rn(0.5f, wa));
    const float cya = __fadd_rn(ay1, __fmul_rn(0.5f, ha));

    const float* d = deltas + (size_t)(img * R_TOT + r) * 4;
    const float dx = d[0], dy = d[1];
    const float dw = fminf(d[2], BBOX_CLIP);
    const float dh = fminf(d[3], BBOX_CLIP);
    const float cx = __fadd_rn(__fmul_rn(dx, wa), cxa);
    const float cy = __fadd_rn(__fmul_rn(dy, ha), cya);
    const float w = __fmul_rn(expf(dw), wa);
    const float h = __fmul_rn(expf(dh), ha);

    float x1 = __fsub_rn(cx, __fmul_rn(0.5f, w));
    float y1 = __fsub_rn(cy, __fmul_rn(0.5f, h));
    float x2 = __fadd_rn(cx, __fmul_rn(0.5f, w));
    float y2 = __fadd_rn(cy, __fmul_rn(0.5f, h));
    x1 = fminf(fmaxf(x1, 0.0f), IMG_MAX);
    y1 = fminf(fmaxf(y1, 0.0f), IMG_MAX);
    x2 = fminf(fmaxf(x2, 0.0f), IMG_MAX);
    y2 = fminf(fmaxf(y2, 0.0f), IMG_MAX);

    bool valid = (__fsub_rn(x2, x1) >= MIN_SIZE) &&
                 (__fsub_rn(y2, y1) >= MIN_SIZE) &&
                 (score >= 0.0f);
    g_cand_box[t]   = make_float4(x1, y1, x2, y2);
    g_cand_score[t] = score;
    g_cand_valid[t] = valid ? 1 : 0;
}

// ---------------- K3: per-image global sort (stable tie-break by position) --
// key = mono(masked_score) << 13 | (8191 - slot); ascending sort, read reversed
// => score descending, ties by slot (== reference position) ascending.
__global__ void sort_kernel() {
    extern __shared__ unsigned long long sk[];   // 8192 * 8B = 64KB
    const int img = blockIdx.x;
    const int tid = threadIdx.x;

    for (int i = tid; i < 8192; i += 1024) {
        unsigned long long key = 0ull;
        if (i < K_TOT) {
            float s = g_cand_valid[img * K_TOT + i] ? g_cand_score[img * K_TOT + i] : -1.0f;
            key = ((unsigned long long)mono_key(s) << 13) | (unsigned)(8191 - i);
        }
        sk[i] = key;
    }
    __syncthreads();

    for (int k2 = 2; k2 <= 8192; k2 <<= 1) {
        for (int j = k2 >> 1; j > 0; j >>= 1) {
            for (int t = tid; t < 4096; t += 1024) {
                int i = ((t & ~(j - 1)) << 1) | (t & (j - 1));
                int p = i + j;
                bool dir = ((i & k2) == 0);
                unsigned long long A = sk[i], B = sk[p];
                if ((A > B) == dir) { sk[i] = B; sk[p] = A; }
            }
            __syncthreads();
        }
    }
    for (int p = tid; p < K_TOT; p += 1024)
        g_sorted_slot[img * K_TOT + p] = 8191 - (int)(sk[8191 - p] & 0x1FFFull);
}

// ---------------- K4: per-(img,level) greedy NMS on OFFSET boxes -------------
__global__ void nms_kernel() {
    const int img = blockIdx.x / N_LVL;
    const int lvl = blockIdx.x % N_LVL;
    const int s0 = c_soff[lvl];
    const int s1 = s0 + c_ksel[lvl];
    const int tid = threadIdx.x;
    const float off = (float)lvl * 801.0f;   // lvl * (max(H,W)+1)

    __shared__ float4 sbox[1000];            // OFFSET boxes (replicates ref quantization)
    __shared__ float  sarea[1000];
    __shared__ int    sgpos[1000];
    __shared__ unsigned char ssup[1000];

    int m = 0;
    for (int start = 0; start < K_TOT; start += 1024) {
        int p = start + tid;
        bool flag = false;
        int slot = -1;
        if (p < K_TOT) {
            slot = g_sorted_slot[img * K_TOT + p];
            flag = (slot >= s0) && (slot < s1) && (g_cand_valid[img * K_TOT + slot] != 0);
        }
        int total;
        int pos = block_scan_flag(flag, &total);
        if (flag) {
            int li = m + pos;
            float4 b = g_cand_box[img * K_TOT + slot];
            float ox1 = __fadd_rn(b.x, off);
            float oy1 = __fadd_rn(b.y, off);
            float ox2 = __fadd_rn(b.z, off);
            float oy2 = __fadd_rn(b.w, off);
            sbox[li]  = make_float4(ox1, oy1, ox2, oy2);
            sarea[li] = __fmul_rn(__fsub_rn(ox2, ox1), __fsub_rn(oy2, oy1));
            sgpos[li] = p;
            ssup[li]  = 0;
        }
        m += total;
    }
    __syncthreads();

    for (int i = 0; i < m; ++i) {
        __syncthreads();
        if (ssup[i]) continue;
        if (tid == 0) g_keep[img * K_TOT + sgpos[i]] = 1;
        int j = i + 1 + tid;
        if (j < m) {
            float4 bi = sbox[i], bj = sbox[j];
            float lx = fmaxf(bi.x, bj.x), ly = fmaxf(bi.y, bj.y);
            float rx = fminf(bi.z, bj.z), ry = fminf(bi.w, bj.w);
            float wx = fmaxf(__fsub_rn(rx, lx), 0.0f);
            float wy = fmaxf(__fsub_rn(ry, ly), 0.0f);
            float inter = __fmul_rn(wx, wy);
            float denom = __fadd_rn(__fsub_rn(__fadd_rn(sarea[i], sarea[j]), inter), 1e-9f);
            float iou = __fdiv_rn(inter, denom);
            if (iou > NMS_THRESH) ssup[j] = 1;
        }
    }
}

// ---------------- K5: compact kept (global score order) into outputs --------
__global__ void compact_kernel(float* __restrict__ out) {
    const int img = blockIdx.x;
    const int tid = threadIdx.x;
    float* out_b = out + img * (POST_NMS * 4);
    float* out_s = out + N_IMG * POST_NMS * 4 + img * POST_NMS;

    int rank_base = 0;
    for (int start = 0; start < K_TOT; start += 1024) {
        int p = start + tid;
        bool flag = (p < K_TOT) && (g_keep[img * K_TOT + p] != 0);
        int total;
        int pos = block_scan_flag(flag, &total);
        if (flag) {
            int rank = rank_base + pos;
            if (rank < POST_NMS) {
                int slot = g_sorted_slot[img * K_TOT + p];
                float4 b = g_cand_box[img * K_TOT + slot];
                out_b[rank * 4 + 0] = b.x;
                out_b[rank * 4 + 1] = b.y;
                out_b[rank * 4 + 2] = b.z;
                out_b[rank * 4 + 3] = b.w;
                out_s[rank] = g_cand_score[img * K_TOT + slot];
            }
        }
        rank_base += total;
    }
    int startr = rank_base < POST_NMS ? rank_base : POST_NMS;
    for (int r2 = startr + tid; r2 < POST_NMS; r2 += 1024) {
        out_b[r2 * 4 + 0] = 0.0f;
        out_b[r2 * 4 + 1] = 0.0f;
        out_b[r2 * 4 + 2] = 0.0f;
        out_b[r2 * 4 + 3] = 0.0f;
        out_s[r2] = -1.0f;
    }
}

// ---------------- launch -----------------------------------------------------
extern "C" void kernel_launch(void* const* d_in, const int* in_sizes, int n_in,
                              void* d_out, int out_size) {
    const float* objectness = (const float*)d_in[0];   // [2, 159882]
    const float* deltas     = (const float*)d_in[1];   // [2, 159882, 4]
    const float* anchors    = (const float*)d_in[2];   // [159882, 4]
    float* out = (float*)d_out;                        // boxes [2,1000,4] ++ scores [2,1000]

    cudaFuncSetAttribute(sort_kernel, cudaFuncAttributeMaxDynamicSharedMemorySize, 65536);

    topk_kernel<<<N_IMG * N_LVL, 1024>>>(objectness);
    decode_kernel<<<(N_IMG * K_TOT + 255) / 256, 256>>>(objectness, deltas, anchors);
    sort_kernel<<<N_IMG, 1024, 65536>>>();
    nms_kernel<<<N_IMG * N_LVL, 1024>>>();
    compact_kernel<<<N_IMG, 1024>>>(out);
}